// round 10
// baseline (speedup 1.0000x reference)
#include <cuda_runtime.h>
#include <cuda_fp16.h>

// MorphologicalDilation: out[b,ho,wo,f] = max_{k} ( x[b, ho+ki, wo+kj, 0] + w[k, f] )
// x: (16,256,256,1) f32   w: (9,32) f32   out: (16,254,254,32) f32
//
// R10: fp16x2 math (R9) + 12-CTA/SM pin + 2 output rows per iteration with
// independent reduction trees (double ILP per warp).

#define H_IN   256
#define W_IN   256
#define NF     32
#define H_OUT  254
#define W_OUT  254
#define TILE_H 16
#define TILE_W 16
#define XS_W   18
#define XS_H   18
#define OSTRIDE (W_OUT * NF)

// One output row for 4 filters (2 half2 lanes): 9 taps, tree max depth 4.
__device__ __forceinline__ float4 win_row(
    const __half2* a, const __half2* b, const __half2* c,
    const __half2 (*wv)[2])
{
    __half2 acc[2];
#pragma unroll
    for (int h = 0; h < 2; ++h) {
        __half2 t0 = __hmax2(__hadd2(a[0], wv[0][h]), __hadd2(a[1], wv[1][h]));
        __half2 t1 = __hmax2(__hadd2(a[2], wv[2][h]), __hadd2(b[0], wv[3][h]));
        __half2 t2 = __hmax2(__hadd2(b[1], wv[4][h]), __hadd2(b[2], wv[5][h]));
        __half2 t3 = __hmax2(__hadd2(c[0], wv[6][h]), __hadd2(c[1], wv[7][h]));
        __half2 t4 = __hadd2(c[2], wv[8][h]);
        acc[h] = __hmax2(__hmax2(__hmax2(t0, t1), __hmax2(t2, t3)), t4);
    }
    float2 f01 = __half22float2(acc[0]);
    float2 f23 = __half22float2(acc[1]);
    return make_float4(f01.x, f01.y, f23.x, f23.y);
}

template<int NR>
__device__ __forceinline__ void do_column(
    const __half2 (*xs)[XS_W], int pos, float* __restrict__ op,
    const __half2 (*wv)[2])
{
    // 4-row rotating window, two outputs per iteration -> independent trees.
    __half2 p[4][3];
#pragma unroll
    for (int r = 0; r < 2; ++r) {
        p[r][0] = xs[r][pos];
        p[r][1] = xs[r][pos + 1];
        p[r][2] = xs[r][pos + 2];
    }

    static_assert(NR % 2 == 0, "NR must be even");
#pragma unroll
    for (int s = 0; s < NR; s += 2) {
        const int c2 = (s + 2) % 4, c3 = (s + 3) % 4;
        // Issue all 6 loads for both new rows first.
        p[c2][0] = xs[s + 2][pos];
        p[c2][1] = xs[s + 2][pos + 1];
        p[c2][2] = xs[s + 2][pos + 2];
        p[c3][0] = xs[s + 3][pos];
        p[c3][1] = xs[s + 3][pos + 1];
        p[c3][2] = xs[s + 3][pos + 2];

        const int r0 = s % 4, r1 = (s + 1) % 4;
        // Two fully independent reduction trees.
        float4 acc0 = win_row(p[r0], p[r1], p[c2], wv);
        float4 acc1 = win_row(p[r1], p[c2], p[c3], wv);

        *reinterpret_cast<float4*>(op + s * OSTRIDE)       = acc0;
        *reinterpret_cast<float4*>(op + (s + 1) * OSTRIDE) = acc1;
    }
}

__global__ __launch_bounds__(128, 12)
void dilation_kernel(const float* __restrict__ x,
                     const float* __restrict__ w,
                     float* __restrict__ out)
{
    __shared__ __half2 xs[XS_H][XS_W];   // dup-packed {x,x} taps

    const int tid = threadIdx.x;
    const int wo0 = blockIdx.x * TILE_W;
    const int ho0 = blockIdx.y * TILE_H;
    const int b   = blockIdx.z;

    const int nr    = min(TILE_H, H_OUT - ho0);   // 16 or 14 (both even)
    const int nrows = nr + 2;

    const float* xg = x + (b * H_IN + ho0) * W_IN;
    for (int i = tid; i < nrows * XS_W; i += 128) {
        const int r  = i / XS_W;
        const int c  = i - r * XS_W;
        const int gc = min(wo0 + c, W_IN - 1);
        xs[r][c] = __half2half2(__float2half_rn(xg[r * W_IN + gc]));
    }

    const int pos   = tid >> 3;
    const int fbase = (tid & 7) << 2;
    __half2 wv[9][2];
#pragma unroll
    for (int k = 0; k < 9; ++k) {
        float4 q = *reinterpret_cast<const float4*>(&w[k * NF + fbase]);
        wv[k][0] = __floats2half2_rn(q.x, q.y);
        wv[k][1] = __floats2half2_rn(q.z, q.w);
    }

    __syncthreads();

    const int wo = wo0 + pos;
    if (wo >= W_OUT) return;

    float* op = out + ((b * H_OUT + ho0) * W_OUT + wo) * NF + fbase;

    if (nr == TILE_H) do_column<TILE_H>(xs, pos, op, wv);
    else              do_column<H_OUT % TILE_H>(xs, pos, op, wv);
}

extern "C" void kernel_launch(void* const* d_in, const int* in_sizes, int n_in,
                              void* d_out, int out_size)
{
    const float* x = (const float*)d_in[0];
    const float* w = (const float*)d_in[1];
    float* out = (float*)d_out;

    const int B = in_sizes[0] / (H_IN * W_IN);   // 16

    dim3 grid((W_OUT + TILE_W - 1) / TILE_W,
              (H_OUT + TILE_H - 1) / TILE_H, B);   // (16,16,16)
    dilation_kernel<<<grid, 128>>>(x, w, out);
}